// round 14
// baseline (speedup 1.0000x reference)
#include <cuda_runtime.h>
#include <cuda_fp16.h>
#include <cstdint>
#include <math.h>

#define D_MODEL 1024
#define NHEAD 16
#define HDIM 64
#define SEQ 2048
#define NBATCH 2
#define NROWS (NBATCH * SEQ)          // 4096
#define EPS_V 1e-6f
#define NSPLIT 16

typedef uint16_t u16;
typedef uint32_t u32;

// ---------------- scratch (device globals; no allocation allowed) -----------
__device__ float g_kv[NBATCH * NHEAD * HDIM * HDIM];
__device__ float g_ksum[NBATCH * NHEAD * HDIM];

// fp16 planes
__device__ __align__(16) u16 g_xh[NROWS * D_MODEL];
__device__ __align__(16) u16 g_qh[NROWS * D_MODEL];
__device__ __align__(16) u16 g_kh[NROWS * D_MODEL];
__device__ __align__(16) u16 g_vh[NROWS * D_MODEL];
__device__ __align__(16) u16 g_oh[NROWS * D_MODEL];
// packed weights: rows [0,1024)=wq, [1024,2048)=wk, [2048,3072)=wv, [3072,4096)=wo
__device__ __align__(16) u16 g_wh[4 * D_MODEL * D_MODEL];

__device__ __forceinline__ u32 smem_u32(const void* p) {
    u32 a;
    asm("{ .reg .u64 t; cvta.to.shared.u64 t, %1; cvt.u32.u64 %0, t; }"
        : "=r"(a) : "l"(p));
    return a;
}

__device__ __forceinline__ void ldsm4(u32* r, u32 addr) {
    asm volatile("ldmatrix.sync.aligned.m8n8.x4.shared.b16 {%0,%1,%2,%3}, [%4];"
                 : "=r"(r[0]), "=r"(r[1]), "=r"(r[2]), "=r"(r[3]) : "r"(addr));
}

__device__ __forceinline__ void mma16816h(float* c, const u32* a, u32 b0, u32 b1) {
    asm volatile(
        "mma.sync.aligned.m16n8k16.row.col.f32.f16.f16.f32 "
        "{%0,%1,%2,%3}, {%4,%5,%6,%7}, {%8,%9}, {%0,%1,%2,%3};"
        : "+f"(c[0]), "+f"(c[1]), "+f"(c[2]), "+f"(c[3])
        : "r"(a[0]), "r"(a[1]), "r"(a[2]), "r"(a[3]), "r"(b0), "r"(b1));
}

#define CP16(dst, src) \
    asm volatile("cp.async.cg.shared.global [%0], [%1], 16;" :: "r"(dst), "l"(src))
#define CP_COMMIT() asm volatile("cp.async.commit_group;" ::: "memory")
#define CP_WAIT0()  asm volatile("cp.async.wait_group 0;" ::: "memory")
#define CP_WAIT1()  asm volatile("cp.async.wait_group 1;" ::: "memory")

__device__ __forceinline__ uint2 cvt4h(float4 f) {
    half2 a = __floats2half2_rn(f.x, f.y);
    half2 b = __floats2half2_rn(f.z, f.w);
    return make_uint2(*(u32*)&a, *(u32*)&b);
}

__device__ __forceinline__ void h8_to_f8(uint4 v, float* o) {
    float2 f0 = __half22float2(*(half2*)&v.x);
    float2 f1 = __half22float2(*(half2*)&v.y);
    float2 f2 = __half22float2(*(half2*)&v.z);
    float2 f3 = __half22float2(*(half2*)&v.w);
    o[0] = f0.x; o[1] = f0.y; o[2] = f1.x; o[3] = f1.y;
    o[4] = f2.x; o[5] = f2.y; o[6] = f3.x; o[7] = f3.y;
}

// ---------------- fused conversion + zero pass --------------------------------
// jobs (float4 granularity): [0,1M) x->fp16, [1M,2M) weights->fp16,
// [2M, 2M+32768) zero g_kv, [.., +512) zero g_ksum.
#define XQ4 (NROWS * D_MODEL / 4)            // 1048576
#define WQ4 (D_MODEL * D_MODEL)              // 1048576 (4 x 256K)
#define ZKV4 (NBATCH * NHEAD * HDIM * HDIM / 4)   // 32768
#define ZKS4 (NBATCH * NHEAD * HDIM / 4)          // 512
#define CONV_JOBS (XQ4 + WQ4 + ZKV4 + ZKS4)

__global__ __launch_bounds__(256) void conv_all_kernel(
    const float* __restrict__ x,
    const float* __restrict__ w0, const float* __restrict__ w1,
    const float* __restrict__ w2, const float* __restrict__ w3)
{
    const u32 i = blockIdx.x * 256 + threadIdx.x;
    if (i < XQ4) {
        ((uint2*)g_xh)[i] = cvt4h(((const float4*)x)[i]);
    } else if (i < XQ4 + WQ4) {
        const u32 j = i - XQ4;
        const u32 m = j >> 18;
        const u32 e = j & 0x3FFFF;
        const float* src = (m == 0) ? w0 : (m == 1) ? w1 : (m == 2) ? w2 : w3;
        ((uint2*)g_wh)[((size_t)m << 18) + e] = cvt4h(((const float4*)src)[e]);
    } else if (i < XQ4 + WQ4 + ZKV4) {
        ((float4*)g_kv)[i - XQ4 - WQ4] = make_float4(0.f, 0.f, 0.f, 0.f);
    } else if (i < CONV_JOBS) {
        ((float4*)g_ksum)[i - XQ4 - WQ4 - ZKV4] = make_float4(0.f, 0.f, 0.f, 0.f);
    }
}

// ======================= fp16 GEMM (unchanged from R13) ======================
#define BM 128
#define BN 128
#define PLANE_B 16384
#define STAGE_B (2 * PLANE_B)                // 32768
#define GEMM_SMEM (3 * STAGE_B)              // 98304

template <int OUT16>
__global__ __launch_bounds__(256, 2)
void gemm1t(const u16* __restrict__ Ah, const u16* __restrict__ Wh,
            const float* __restrict__ b0, const float* __restrict__ b1,
            const float* __restrict__ b2,
            void* __restrict__ C0, void* __restrict__ C1, void* __restrict__ C2,
            int M, int K, int actmask)
{
    extern __shared__ __align__(1024) char smem[];
    const u32 sb = smem_u32(smem);

    const int tid = threadIdx.x;
    const int lane = tid & 31, wid = tid >> 5;
    const int wm = wid >> 1, wn = wid & 1;
    const int bm = blockIdx.y * BM;
    const int bng = blockIdx.x * BN;
    const int seg = blockIdx.x >> 3;
    const int bns = bng & 1023;

    const float* bias = (seg == 0) ? b0 : (seg == 1) ? b1 : b2;
    void* C = (seg == 0) ? C0 : (seg == 1) ? C1 : C2;
    const int act = (actmask >> seg) & 1;

    const int NCH = K / 64;

    const int arow_l = (lane & 15);
    const u32 akb = (u32)((lane >> 4) * 16);
    const int brow_l = (lane & 7) + ((lane >> 4) << 3);
    const u32 bkb = (u32)(((lane >> 3) & 1) * 16);

    u32 abase[2], axor[2];
#pragma unroll
    for (int mt = 0; mt < 2; ++mt) {
        const int r = wm * 32 + mt * 16 + arow_l;
        abase[mt] = (u32)(r * 128);
        axor[mt] = (u32)((r & 7) << 4);
    }
    u32 bbase[4], bxor[4];
#pragma unroll
    for (int p = 0; p < 4; ++p) {
        const int r = wn * 64 + p * 16 + brow_l;
        bbase[p] = (u32)(r * 128);
        bxor[p] = (u32)((r & 7) << 4);
    }

    float acc[2][8][4];
#pragma unroll
    for (int i = 0; i < 2; ++i)
#pragma unroll
        for (int j = 0; j < 8; ++j)
#pragma unroll
            for (int d = 0; d < 4; ++d) acc[i][j][d] = 0.f;

    auto load_chunk = [&](int c, int stage) {
        const u32 bufb = sb + stage * STAGE_B;
        const size_t kc = (size_t)c * 64;
#pragma unroll
        for (int i = 0; i < 4; ++i) {
            const int idx = i * 256 + tid;
            const int r = idx >> 3, c16 = idx & 7;
            const u32 dsto = (u32)(r * 128 + ((c16 * 16) ^ ((r & 7) * 16)));
            const size_t asrc = (size_t)(bm + r) * K + kc + c16 * 8;
            const size_t wsrc = (size_t)(bng + r) * K + kc + c16 * 8;
            CP16(bufb + dsto, Ah + asrc);
            CP16(bufb + PLANE_B + dsto, Wh + wsrc);
        }
        CP_COMMIT();
    };

    load_chunk(0, 0);
    load_chunk(1, 1);

    int stage = 0;
    for (int c = 0; c < NCH; ++c) {
        if (c == NCH - 1) { CP_WAIT0(); } else { CP_WAIT1(); }
        __syncthreads();
        if (c + 2 < NCH) {
            int s2 = stage + 2; if (s2 >= 3) s2 -= 3;
            load_chunk(c + 2, s2);
        }

        const u32 bufb = sb + stage * STAGE_B;
        const u32 AHb = bufb, WHb = bufb + PLANE_B;

#pragma unroll
        for (int ks = 0; ks < 4; ++ks) {
            u32 ah[2][4], bh[4][4];
#pragma unroll
            for (int mt = 0; mt < 2; ++mt) {
                const u32 t = ((u32)(ks * 32) + akb) ^ axor[mt];
                ldsm4(ah[mt], AHb + abase[mt] + t);
            }
#pragma unroll
            for (int p = 0; p < 4; ++p) {
                const u32 t = ((u32)(ks * 32) + bkb) ^ bxor[p];
                ldsm4(bh[p], WHb + bbase[p] + t);
            }
#pragma unroll
            for (int mt = 0; mt < 2; ++mt)
#pragma unroll
                for (int nt = 0; nt < 8; ++nt) {
                    const int p = nt >> 1, q = (nt & 1) * 2;
                    mma16816h(acc[mt][nt], ah[mt], bh[p][q], bh[p][q + 1]);
                }
        }
        ++stage; if (stage == 3) stage = 0;
    }

    const int erow = bm + wm * 32 + (lane >> 2);
    const int ecol0 = bns + wn * 64 + (lane & 3) * 2;
#pragma unroll
    for (int nt = 0; nt < 8; ++nt) {
        const int col = ecol0 + nt * 8;
        const float bb0 = bias[col], bb1 = bias[col + 1];
#pragma unroll
        for (int mt = 0; mt < 2; ++mt) {
#pragma unroll
            for (int h = 0; h < 2; ++h) {
                const int row = erow + mt * 16 + h * 8;
                float v0 = acc[mt][nt][2 * h] + bb0;
                float v1 = acc[mt][nt][2 * h + 1] + bb1;
                if (act) {
                    v0 = (v0 > 0.f) ? (v0 + 1.f) : __expf(v0);
                    v1 = (v1 > 0.f) ? (v1 + 1.f) : __expf(v1);
                }
                if (OUT16) {
                    half2 hp = __floats2half2_rn(v0, v1);
                    *(u32*)((u16*)C + (size_t)row * D_MODEL + col) = *(u32*)&hp;
                } else {
                    *(float2*)((float*)C + (size_t)row * D_MODEL + col) =
                        make_float2(v0, v1);
                }
            }
        }
    }
}

// ---------------- kv = kf^T @ v per (b,h), split-K -------------------------
// 64 threads, 8x8 per thread (balanced LDS:FMA). fp16 in, fp32 acc.
__global__ __launch_bounds__(64)
void kv_kernel()
{
    const int bh = blockIdx.x;
    const int split = blockIdx.y;
    const int b = bh >> 4, h = bh & 15;
    const int j0 = b * SEQ + split * (SEQ / NSPLIT);    // 128 rows per split

    const u16* Kp = g_kh + (size_t)j0 * D_MODEL + h * HDIM;
    const u16* Vp = g_vh + (size_t)j0 * D_MODEL + h * HDIM;

    __shared__ __align__(16) float ks[32][64];
    __shared__ __align__(16) float vs[32][64];

    const int t = threadIdx.x;
    const int dg = t >> 3, eg = t & 7;
    const int d0 = dg * 8, e0 = eg * 8;

    float acc[8][8];
#pragma unroll
    for (int i = 0; i < 8; ++i)
#pragma unroll
        for (int j = 0; j < 8; ++j) acc[i][j] = 0.f;
    float sacc[8] = {0.f, 0.f, 0.f, 0.f, 0.f, 0.f, 0.f, 0.f};

    for (int it = 0; it < (SEQ / NSPLIT) / 32; ++it) {   // 4 iterations
        const int rbase = it * 32;
        // 32 rows x 8 uint4-chunks = 256 jobs; 64 threads x 4
#pragma unroll
        for (int i = 0; i < 4; ++i) {
            const int idx = i * 64 + t;
            const int r = idx >> 3, c8 = (idx & 7) * 8;
            float tmp[8];
            h8_to_f8(*(const uint4*)(Kp + (size_t)(rbase + r) * D_MODEL + c8), tmp);
#pragma unroll
            for (int j = 0; j < 8; ++j) ks[r][c8 + j] = tmp[j];
            h8_to_f8(*(const uint4*)(Vp + (size_t)(rbase + r) * D_MODEL + c8), tmp);
#pragma unroll
            for (int j = 0; j < 8; ++j) vs[r][c8 + j] = tmp[j];
        }
        __syncthreads();
#pragma unroll
        for (int r = 0; r < 32; ++r) {
            float kd[8], ve[8];
            *(float4*)&kd[0] = *(const float4*)&ks[r][d0];
            *(float4*)&kd[4] = *(const float4*)&ks[r][d0 + 4];
            *(float4*)&ve[0] = *(const float4*)&vs[r][e0];
            *(float4*)&ve[4] = *(const float4*)&vs[r][e0 + 4];
#pragma unroll
            for (int i = 0; i < 8; ++i)
#pragma unroll
                for (int j = 0; j < 8; ++j)
                    acc[i][j] = fmaf(kd[i], ve[j], acc[i][j]);
            if (eg == 0) {
#pragma unroll
                for (int i = 0; i < 8; ++i) sacc[i] += kd[i];
            }
        }
        __syncthreads();
    }

    float* kvp = g_kv + (size_t)bh * HDIM * HDIM;
#pragma unroll
    for (int i = 0; i < 8; ++i)
#pragma unroll
        for (int j = 0; j < 8; ++j)
            atomicAdd(&kvp[(d0 + i) * HDIM + e0 + j], acc[i][j]);
    if (eg == 0) {
#pragma unroll
        for (int i = 0; i < 8; ++i)
            atomicAdd(&g_ksum[bh * HDIM + d0 + i], sacc[i]);
    }
}

// ---------------- attended = (qf @ kv) / max(qf . ksum, eps) -----------------
// 64 threads, 8x8 per thread; q stored transposed in smem (conflict-free).
__global__ __launch_bounds__(64)
void attend_kernel()
{
    const int tile = blockIdx.x;
    const int bh = blockIdx.y;
    const int b = bh >> 4, h = bh & 15;
    const int row0 = b * SEQ + tile * 64;

    __shared__ __align__(16) float kvs[64][64];
    __shared__ __align__(16) float qsT[64][64];   // [d][row]
    __shared__ float ksum_s[64];

    const int t = threadIdx.x;

    const float* kvp = g_kv + (size_t)bh * HDIM * HDIM;
#pragma unroll
    for (int i = 0; i < 16; ++i)
        ((float4*)kvs)[i * 64 + t] = ((const float4*)kvp)[i * 64 + t];
    if (t < 64) ksum_s[t] = g_ksum[bh * HDIM + t];

    const u16* Qp = g_qh + (size_t)row0 * D_MODEL + h * HDIM;
    // 64 rows x 8 uint4 = 512 jobs; 64 threads x 8; store transposed
#pragma unroll
    for (int i = 0; i < 8; ++i) {
        const int idx = i * 64 + t;
        const int r = idx >> 3, c8 = (idx & 7) * 8;
        float tmp[8];
        h8_to_f8(*(const uint4*)(Qp + (size_t)r * D_MODEL + c8), tmp);
#pragma unroll
        for (int j = 0; j < 8; ++j) qsT[c8 + j][r] = tmp[j];
    }
    __syncthreads();

    const int rg = t >> 3, cg = t & 7;
    const int r0 = rg * 8, c0 = cg * 8;

    float num[8][8];
#pragma unroll
    for (int i = 0; i < 8; ++i)
#pragma unroll
        for (int j = 0; j < 8; ++j) num[i][j] = 0.f;
    float den[8] = {0.f, 0.f, 0.f, 0.f, 0.f, 0.f, 0.f, 0.f};

    for (int d = 0; d < 64; ++d) {
        float qv[8], kva[8];
        *(float4*)&qv[0] = *(const float4*)&qsT[d][r0];
        *(float4*)&qv[4] = *(const float4*)&qsT[d][r0 + 4];
        *(float4*)&kva[0] = *(const float4*)&kvs[d][c0];
        *(float4*)&kva[4] = *(const float4*)&kvs[d][c0 + 4];
        const float kd = ksum_s[d];
#pragma unroll
        for (int i = 0; i < 8; ++i) {
#pragma unroll
            for (int j = 0; j < 8; ++j)
                num[i][j] = fmaf(qv[i], kva[j], num[i][j]);
            den[i] = fmaf(qv[i], kd, den[i]);
        }
    }

#pragma unroll
    for (int i = 0; i < 8; ++i) {
        const float inv = 1.f / fmaxf(den[i], EPS_V);
        float4 lo = make_float4(num[i][0] * inv, num[i][1] * inv,
                                num[i][2] * inv, num[i][3] * inv);
        float4 hi = make_float4(num[i][4] * inv, num[i][5] * inv,
                                num[i][6] * inv, num[i][7] * inv);
        uint2 a = cvt4h(lo), c = cvt4h(hi);
        *(uint4*)(g_oh + (size_t)(row0 + r0 + i) * D_MODEL + h * HDIM + c0) =
            make_uint4(a.x, a.y, c.x, c.y);
    }
}

// ---------------- launch -----------------------------------------------------
extern "C" void kernel_launch(void* const* d_in, const int* in_sizes, int n_in,
                              void* d_out, int out_size)
{
    const float* x  = (const float*)d_in[0];
    const float* wq = (const float*)d_in[1];
    const float* bq = (const float*)d_in[2];
    const float* wk = (const float*)d_in[3];
    const float* bk = (const float*)d_in[4];
    const float* wv = (const float*)d_in[5];
    const float* bv = (const float*)d_in[6];
    const float* wo = (const float*)d_in[7];
    const float* bo = (const float*)d_in[8];
    float* out = (float*)d_out;

    const int M = in_sizes[0] / D_MODEL;   // 4096

    u16 *xh, *qh, *kh, *vh, *oh, *wh;
    cudaGetSymbolAddress((void**)&xh, g_xh);
    cudaGetSymbolAddress((void**)&qh, g_qh);
    cudaGetSymbolAddress((void**)&kh, g_kh);
    cudaGetSymbolAddress((void**)&vh, g_vh);
    cudaGetSymbolAddress((void**)&oh, g_oh);
    cudaGetSymbolAddress((void**)&wh, g_wh);

    cudaFuncSetAttribute(gemm1t<1>, cudaFuncAttributeMaxDynamicSharedMemorySize, GEMM_SMEM);
    cudaFuncSetAttribute(gemm1t<0>, cudaFuncAttributeMaxDynamicSharedMemorySize, GEMM_SMEM);

    // 1: fused conversion + zeroing
    conv_all_kernel<<<(CONV_JOBS + 255) / 256, 256>>>(x, wq, wk, wv, wo);

    // 2: fused QKV projection -> fp16 planes
    gemm1t<1><<<dim3(3 * D_MODEL / BN, M / BM), 256, GEMM_SMEM>>>(
        xh, wh,
        bq, bk, bv, qh, kh, vh,
        M, D_MODEL, 0b011);

    // 3,4: linear-attention middle
    kv_kernel<<<dim3(NBATCH * NHEAD, NSPLIT), 64>>>();
    attend_kernel<<<dim3(SEQ / 64, NBATCH * NHEAD), 64>>>();

    // 5: output projection (fp32 out)
    gemm1t<0><<<dim3(D_MODEL / BN, M / BM), 256, GEMM_SMEM>>>(
        oh, wh + (size_t)3 * D_MODEL * D_MODEL,
        bo, bo, bo, out, out, out,
        M, D_MODEL, 0);
}

// round 15
// speedup vs baseline: 1.1967x; 1.1967x over previous
#include <cuda_runtime.h>
#include <cuda_fp16.h>
#include <cstdint>
#include <math.h>

#define D_MODEL 1024
#define NHEAD 16
#define HDIM 64
#define SEQ 2048
#define NBATCH 2
#define NROWS (NBATCH * SEQ)          // 4096
#define EPS_V 1e-6f
#define NSPLIT 8

typedef uint16_t u16;
typedef uint32_t u32;

// ---------------- scratch (device globals; no allocation allowed) -----------
__device__ float g_kv[NBATCH * NHEAD * HDIM * HDIM];
__device__ float g_ksum[NBATCH * NHEAD * HDIM];

// fp16 planes
__device__ __align__(16) u16 g_xh[NROWS * D_MODEL];
__device__ __align__(16) u16 g_qh[NROWS * D_MODEL];
__device__ __align__(16) u16 g_kh[NROWS * D_MODEL];
__device__ __align__(16) u16 g_vh[NROWS * D_MODEL];
__device__ __align__(16) u16 g_oh[NROWS * D_MODEL];
__device__ __align__(16) u16 g_wh[4 * D_MODEL * D_MODEL];

__device__ __forceinline__ u32 smem_u32(const void* p) {
    u32 a;
    asm("{ .reg .u64 t; cvta.to.shared.u64 t, %1; cvt.u32.u64 %0, t; }"
        : "=r"(a) : "l"(p));
    return a;
}

__device__ __forceinline__ void ldsm4(u32* r, u32 addr) {
    asm volatile("ldmatrix.sync.aligned.m8n8.x4.shared.b16 {%0,%1,%2,%3}, [%4];"
                 : "=r"(r[0]), "=r"(r[1]), "=r"(r[2]), "=r"(r[3]) : "r"(addr));
}

__device__ __forceinline__ void ldsm4t(u32* r, u32 addr) {
    asm volatile("ldmatrix.sync.aligned.m8n8.x4.trans.shared.b16 {%0,%1,%2,%3}, [%4];"
                 : "=r"(r[0]), "=r"(r[1]), "=r"(r[2]), "=r"(r[3]) : "r"(addr));
}

__device__ __forceinline__ void mma16816h(float* c, const u32* a, u32 b0, u32 b1) {
    asm volatile(
        "mma.sync.aligned.m16n8k16.row.col.f32.f16.f16.f32 "
        "{%0,%1,%2,%3}, {%4,%5,%6,%7}, {%8,%9}, {%0,%1,%2,%3};"
        : "+f"(c[0]), "+f"(c[1]), "+f"(c[2]), "+f"(c[3])
        : "r"(a[0]), "r"(a[1]), "r"(a[2]), "r"(a[3]), "r"(b0), "r"(b1));
}

#define CP16(dst, src) \
    asm volatile("cp.async.cg.shared.global [%0], [%1], 16;" :: "r"(dst), "l"(src))
#define CP_COMMIT() asm volatile("cp.async.commit_group;" ::: "memory")
#define CP_WAIT0()  asm volatile("cp.async.wait_group 0;" ::: "memory")
#define CP_WAIT1()  asm volatile("cp.async.wait_group 1;" ::: "memory")

__device__ __forceinline__ uint2 cvt4h(float4 f) {
    half2 a = __floats2half2_rn(f.x, f.y);
    half2 b = __floats2half2_rn(f.z, f.w);
    return make_uint2(*(u32*)&a, *(u32*)&b);
}

// ---------------- fused conversion + zero pass --------------------------------
#define XQ4 (NROWS * D_MODEL / 4)
#define WQ4 (D_MODEL * D_MODEL)
#define ZKV4 (NBATCH * NHEAD * HDIM * HDIM / 4)
#define ZKS4 (NBATCH * NHEAD * HDIM / 4)
#define CONV_JOBS (XQ4 + WQ4 + ZKV4 + ZKS4)

__global__ __launch_bounds__(256) void conv_all_kernel(
    const float* __restrict__ x,
    const float* __restrict__ w0, const float* __restrict__ w1,
    const float* __restrict__ w2, const float* __restrict__ w3)
{
    const u32 i = blockIdx.x * 256 + threadIdx.x;
    if (i < XQ4) {
        ((uint2*)g_xh)[i] = cvt4h(((const float4*)x)[i]);
    } else if (i < XQ4 + WQ4) {
        const u32 j = i - XQ4;
        const u32 m = j >> 18;
        const u32 e = j & 0x3FFFF;
        const float* src = (m == 0) ? w0 : (m == 1) ? w1 : (m == 2) ? w2 : w3;
        ((uint2*)g_wh)[((size_t)m << 18) + e] = cvt4h(((const float4*)src)[e]);
    } else if (i < XQ4 + WQ4 + ZKV4) {
        ((float4*)g_kv)[i - XQ4 - WQ4] = make_float4(0.f, 0.f, 0.f, 0.f);
    } else if (i < CONV_JOBS) {
        ((float4*)g_ksum)[i - XQ4 - WQ4 - ZKV4] = make_float4(0.f, 0.f, 0.f, 0.f);
    }
}

// ======================= fp16 GEMM (unchanged, R13-validated) ================
#define BM 128
#define BN 128
#define PLANE_B 16384
#define STAGE_B (2 * PLANE_B)
#define GEMM_SMEM (3 * STAGE_B)

template <int OUT16>
__global__ __launch_bounds__(256, 2)
void gemm1t(const u16* __restrict__ Ah, const u16* __restrict__ Wh,
            const float* __restrict__ b0, const float* __restrict__ b1,
            const float* __restrict__ b2,
            void* __restrict__ C0, void* __restrict__ C1, void* __restrict__ C2,
            int M, int K, int actmask)
{
    extern __shared__ __align__(1024) char smem[];
    const u32 sb = smem_u32(smem);

    const int tid = threadIdx.x;
    const int lane = tid & 31, wid = tid >> 5;
    const int wm = wid >> 1, wn = wid & 1;
    const int bm = blockIdx.y * BM;
    const int bng = blockIdx.x * BN;
    const int seg = blockIdx.x >> 3;
    const int bns = bng & 1023;

    const float* bias = (seg == 0) ? b0 : (seg == 1) ? b1 : b2;
    void* C = (seg == 0) ? C0 : (seg == 1) ? C1 : C2;
    const int act = (actmask >> seg) & 1;

    const int NCH = K / 64;

    const int arow_l = (lane & 15);
    const u32 akb = (u32)((lane >> 4) * 16);
    const int brow_l = (lane & 7) + ((lane >> 4) << 3);
    const u32 bkb = (u32)(((lane >> 3) & 1) * 16);

    u32 abase[2], axor[2];
#pragma unroll
    for (int mt = 0; mt < 2; ++mt) {
        const int r = wm * 32 + mt * 16 + arow_l;
        abase[mt] = (u32)(r * 128);
        axor[mt] = (u32)((r & 7) << 4);
    }
    u32 bbase[4], bxor[4];
#pragma unroll
    for (int p = 0; p < 4; ++p) {
        const int r = wn * 64 + p * 16 + brow_l;
        bbase[p] = (u32)(r * 128);
        bxor[p] = (u32)((r & 7) << 4);
    }

    float acc[2][8][4];
#pragma unroll
    for (int i = 0; i < 2; ++i)
#pragma unroll
        for (int j = 0; j < 8; ++j)
#pragma unroll
            for (int d = 0; d < 4; ++d) acc[i][j][d] = 0.f;

    auto load_chunk = [&](int c, int stage) {
        const u32 bufb = sb + stage * STAGE_B;
        const size_t kc = (size_t)c * 64;
#pragma unroll
        for (int i = 0; i < 4; ++i) {
            const int idx = i * 256 + tid;
            const int r = idx >> 3, c16 = idx & 7;
            const u32 dsto = (u32)(r * 128 + ((c16 * 16) ^ ((r & 7) * 16)));
            const size_t asrc = (size_t)(bm + r) * K + kc + c16 * 8;
            const size_t wsrc = (size_t)(bng + r) * K + kc + c16 * 8;
            CP16(bufb + dsto, Ah + asrc);
            CP16(bufb + PLANE_B + dsto, Wh + wsrc);
        }
        CP_COMMIT();
    };

    load_chunk(0, 0);
    load_chunk(1, 1);

    int stage = 0;
    for (int c = 0; c < NCH; ++c) {
        if (c == NCH - 1) { CP_WAIT0(); } else { CP_WAIT1(); }
        __syncthreads();
        if (c + 2 < NCH) {
            int s2 = stage + 2; if (s2 >= 3) s2 -= 3;
            load_chunk(c + 2, s2);
        }

        const u32 bufb = sb + stage * STAGE_B;
        const u32 AHb = bufb, WHb = bufb + PLANE_B;

#pragma unroll
        for (int ks = 0; ks < 4; ++ks) {
            u32 ah[2][4], bh[4][4];
#pragma unroll
            for (int mt = 0; mt < 2; ++mt) {
                const u32 t = ((u32)(ks * 32) + akb) ^ axor[mt];
                ldsm4(ah[mt], AHb + abase[mt] + t);
            }
#pragma unroll
            for (int p = 0; p < 4; ++p) {
                const u32 t = ((u32)(ks * 32) + bkb) ^ bxor[p];
                ldsm4(bh[p], WHb + bbase[p] + t);
            }
#pragma unroll
            for (int mt = 0; mt < 2; ++mt)
#pragma unroll
                for (int nt = 0; nt < 8; ++nt) {
                    const int p = nt >> 1, q = (nt & 1) * 2;
                    mma16816h(acc[mt][nt], ah[mt], bh[p][q], bh[p][q + 1]);
                }
        }
        ++stage; if (stage == 3) stage = 0;
    }

    const int erow = bm + wm * 32 + (lane >> 2);
    const int ecol0 = bns + wn * 64 + (lane & 3) * 2;
#pragma unroll
    for (int nt = 0; nt < 8; ++nt) {
        const int col = ecol0 + nt * 8;
        const float bb0 = bias[col], bb1 = bias[col + 1];
#pragma unroll
        for (int mt = 0; mt < 2; ++mt) {
#pragma unroll
            for (int h = 0; h < 2; ++h) {
                const int row = erow + mt * 16 + h * 8;
                float v0 = acc[mt][nt][2 * h] + bb0;
                float v1 = acc[mt][nt][2 * h + 1] + bb1;
                if (act) {
                    v0 = (v0 > 0.f) ? (v0 + 1.f) : __expf(v0);
                    v1 = (v1 > 0.f) ? (v1 + 1.f) : __expf(v1);
                }
                if (OUT16) {
                    half2 hp = __floats2half2_rn(v0, v1);
                    *(u32*)((u16*)C + (size_t)row * D_MODEL + col) = *(u32*)&hp;
                } else {
                    *(float2*)((float*)C + (size_t)row * D_MODEL + col) =
                        make_float2(v0, v1);
                }
            }
        }
    }
}

// ---------------- kv = kf^T @ v per (b,h) via tensor cores -------------------
// 128 threads / 4 warps; warp w -> d-strip w*16. K=256 rows per block (split).
// A (k) and B (v) both contraction-major -> ldmatrix.trans fragments.
__global__ __launch_bounds__(128)
void kv_kernel()
{
    const int bh = blockIdx.x;
    const int split = blockIdx.y;
    const int b = bh >> 4, h = bh & 15;
    const int j0 = b * SEQ + split * (SEQ / NSPLIT);   // 256 rows

    const u16* Kp = g_kh + (size_t)j0 * D_MODEL + h * HDIM;
    const u16* Vp = g_vh + (size_t)j0 * D_MODEL + h * HDIM;

    __shared__ __align__(16) u16 ks[64 * 64];
    __shared__ __align__(16) u16 vs[64 * 64];
    const u32 ksb = smem_u32(ks), vsb = smem_u32(vs);

    const int tid = threadIdx.x;
    const int lane = tid & 31, wid = tid >> 5;
    const int m0 = wid * 16;                    // d-strip

    // trans-ldsm lane maps
    const int atrow = ((lane >> 4) << 3) + (lane & 7);      // A: j-row within 16
    const u32 atcol = (u32)(((lane >> 3) & 1) * 16);        // bytes within m16
    const int btrow = (((lane >> 3) & 1) << 3) + (lane & 7); // B: j-row within 16
    const u32 btcol = (u32)((lane >> 4) * 16);              // bytes within n16

    float acc[8][4];
#pragma unroll
    for (int j = 0; j < 8; ++j)
#pragma unroll
        for (int d = 0; d < 4; ++d) acc[j][d] = 0.f;
    float ksacc = 0.f;
    const int kcol = tid & 63;                  // column for ksum partial
    const int krhalf = (tid >> 6) * 32;         // rows 0-31 or 32-63

    for (int it = 0; it < 4; ++it) {
        const int jb = it * 64;
        // load 64 rows x 64 halves each: 512 uint4 jobs / 128 threads = 4 each
#pragma unroll
        for (int i = 0; i < 4; ++i) {
            const int idx = i * 128 + tid;
            const int r = idx >> 3, c16 = idx & 7;
            const u32 dsto = (u32)(r * 128 + ((c16 * 16) ^ ((r & 7) * 16)));
            *(uint4*)((char*)ks + dsto) =
                *(const uint4*)(Kp + (size_t)(jb + r) * D_MODEL + c16 * 8);
            *(uint4*)((char*)vs + dsto) =
                *(const uint4*)(Vp + (size_t)(jb + r) * D_MODEL + c16 * 8);
        }
        __syncthreads();

        // ksum partial: each thread sums 32 rows of its column
#pragma unroll 8
        for (int r = 0; r < 32; ++r) {
            const int rr = krhalf + r;
            const u32 off = (u32)(rr * 128 + ((kcol * 2) ^ ((rr & 7) << 4)));
            ksacc += __half2float(*(const half*)((const char*)ks + off));
        }

        // mma: 4 k16-steps
#pragma unroll
        for (int ks16 = 0; ks16 < 4; ++ks16) {
            u32 a[4];
            {
                const int row = ks16 * 16 + atrow;
                const u32 t = (u32)(row * 128 +
                               (((u32)(m0 * 2) + atcol) ^ ((row & 7) << 4)));
                ldsm4t(a, ksb + t);
            }
#pragma unroll
            for (int nb2 = 0; nb2 < 4; ++nb2) {
                u32 bb[4];
                const int row = ks16 * 16 + btrow;
                const u32 t = (u32)(row * 128 +
                               (((u32)(nb2 * 32) + btcol) ^ ((row & 7) << 4)));
                ldsm4t(bb, vsb + t);
                mma16816h(acc[nb2 * 2 + 0], a, bb[0], bb[1]);
                mma16816h(acc[nb2 * 2 + 1], a, bb[2], bb[3]);
            }
        }
        __syncthreads();
    }

    // epilogue: atomics into g_kv; C[m=d][n=e]
    float* kvp = g_kv + (size_t)bh * HDIM * HDIM;
    const int d1 = m0 + (lane >> 2);
    const int nbase = (lane & 3) * 2;
#pragma unroll
    for (int nblk = 0; nblk < 8; ++nblk) {
        const int n = nbase + nblk * 8;
        atomicAdd(&kvp[d1 * HDIM + n],     acc[nblk][0]);
        atomicAdd(&kvp[d1 * HDIM + n + 1], acc[nblk][1]);
        atomicAdd(&kvp[(d1 + 8) * HDIM + n],     acc[nblk][2]);
        atomicAdd(&kvp[(d1 + 8) * HDIM + n + 1], acc[nblk][3]);
    }
    atomicAdd(&g_ksum[bh * HDIM + kcol], ksacc);
}

// ---------------- attended = (qf @ kv) / max(qf . ksum, eps) via mma ---------
// 256 threads / 8 warps; tile 128 rows x 64 e. A=q non-trans, B=kv(fp16) trans.
__global__ __launch_bounds__(256)
void attend_kernel()
{
    const int tile = blockIdx.x;
    const int bh = blockIdx.y;
    const int b = bh >> 4, h = bh & 15;
    const int row0 = b * SEQ + tile * 128;

    __shared__ __align__(16) u16 qs[128 * 64];
    __shared__ __align__(16) u16 kvh[64 * 64];
    __shared__ float ksum_s[64];
    __shared__ float den_s[128];
    const u32 qsb = smem_u32(qs), kvb = smem_u32(kvh);

    const int tid = threadIdx.x;
    const int lane = tid & 31, wid = tid >> 5;
    const int m0 = wid * 16;

    const u16* Qp = g_qh + (size_t)row0 * D_MODEL + h * HDIM;
    // qs: 128 rows x 8 chunks = 1024 jobs / 256 = 4 each
#pragma unroll
    for (int i = 0; i < 4; ++i) {
        const int idx = i * 256 + tid;
        const int r = idx >> 3, c16 = idx & 7;
        const u32 dsto = (u32)(r * 128 + ((c16 * 16) ^ ((r & 7) * 16)));
        *(uint4*)((char*)qs + dsto) =
            *(const uint4*)(Qp + (size_t)r * D_MODEL + c16 * 8);
    }
    // kvh: convert fp32 kv -> fp16 swizzled [d][e]; 1024 float4 jobs / 256 = 4
    const float* kvp = g_kv + (size_t)bh * HDIM * HDIM;
#pragma unroll
    for (int i = 0; i < 4; ++i) {
        const int idx = i * 256 + tid;
        const int r = idx >> 4, c4 = (idx & 15) * 4;
        float4 f = ((const float4*)kvp)[idx];
        uint2 hp = cvt4h(f);
        const u32 dsto = (u32)(r * 128 + ((c4 * 2) ^ ((r & 7) << 4)));
        *(uint2*)((char*)kvh + dsto) = hp;
    }
    if (tid < 64) ksum_s[tid] = g_ksum[bh * HDIM + tid];
    __syncthreads();

    // den: threads 0-127, row = tid
    if (tid < 128) {
        float s = 0.f;
#pragma unroll 16
        for (int d = 0; d < 64; ++d) {
            const u32 off = (u32)(tid * 128 + ((d * 2) ^ ((tid & 7) << 4)));
            s += __half2float(*(const half*)((const char*)qs + off)) * ksum_s[d];
        }
        den_s[tid] = s;
    }
    __syncthreads();

    // mma
    const int arow_l = (lane & 15);
    const u32 akb = (u32)((lane >> 4) * 16);
    const int btrow = (((lane >> 3) & 1) << 3) + (lane & 7);
    const u32 btcol = (u32)((lane >> 4) * 16);

    float acc[8][4];
#pragma unroll
    for (int j = 0; j < 8; ++j)
#pragma unroll
        for (int d = 0; d < 4; ++d) acc[j][d] = 0.f;

#pragma unroll
    for (int ks16 = 0; ks16 < 4; ++ks16) {
        u32 a[4];
        {
            const int row = m0 + arow_l;
            const u32 t = (u32)(row * 128 +
                           (((u32)(ks16 * 32) + akb) ^ ((row & 7) << 4)));
            ldsm4(a, qsb + t);
        }
#pragma unroll
        for (int nb2 = 0; nb2 < 4; ++nb2) {
            u32 bb[4];
            const int row = ks16 * 16 + btrow;
            const u32 t = (u32)(row * 128 +
                           (((u32)(nb2 * 32) + btcol) ^ ((row & 7) << 4)));
            ldsm4t(bb, kvb + t);
            mma16816h(acc[nb2 * 2 + 0], a, bb[0], bb[1]);
            mma16816h(acc[nb2 * 2 + 1], a, bb[2], bb[3]);
        }
    }

    // epilogue
    const int r1 = m0 + (lane >> 2);
    const int r2 = r1 + 8;
    const float inv1 = 1.f / fmaxf(den_s[r1], EPS_V);
    const float inv2 = 1.f / fmaxf(den_s[r2], EPS_V);
    const int nbase = (lane & 3) * 2;
#pragma unroll
    for (int nblk = 0; nblk < 8; ++nblk) {
        const int n = h * HDIM + nblk * 8 + nbase;
        half2 h1 = __floats2half2_rn(acc[nblk][0] * inv1, acc[nblk][1] * inv1);
        half2 h2 = __floats2half2_rn(acc[nblk][2] * inv2, acc[nblk][3] * inv2);
        *(u32*)(g_oh + (size_t)(row0 + r1) * D_MODEL + n) = *(u32*)&h1;
        *(u32*)(g_oh + (size_t)(row0 + r2) * D_MODEL + n) = *(u32*)&h2;
    }
}

// ---------------- launch -----------------------------------------------------
extern "C" void kernel_launch(void* const* d_in, const int* in_sizes, int n_in,
                              void* d_out, int out_size)
{
    const float* x  = (const float*)d_in[0];
    const float* wq = (const float*)d_in[1];
    const float* bq = (const float*)d_in[2];
    const float* wk = (const float*)d_in[3];
    const float* bk = (const float*)d_in[4];
    const float* wv = (const float*)d_in[5];
    const float* bv = (const float*)d_in[6];
    const float* wo = (const float*)d_in[7];
    const float* bo = (const float*)d_in[8];
    float* out = (float*)d_out;

    const int M = in_sizes[0] / D_MODEL;   // 4096

    u16 *xh, *qh, *kh, *vh, *oh, *wh;
    cudaGetSymbolAddress((void**)&xh, g_xh);
    cudaGetSymbolAddress((void**)&qh, g_qh);
    cudaGetSymbolAddress((void**)&kh, g_kh);
    cudaGetSymbolAddress((void**)&vh, g_vh);
    cudaGetSymbolAddress((void**)&oh, g_oh);
    cudaGetSymbolAddress((void**)&wh, g_wh);

    cudaFuncSetAttribute(gemm1t<1>, cudaFuncAttributeMaxDynamicSharedMemorySize, GEMM_SMEM);
    cudaFuncSetAttribute(gemm1t<0>, cudaFuncAttributeMaxDynamicSharedMemorySize, GEMM_SMEM);

    // 1: fused conversion + zeroing
    conv_all_kernel<<<(CONV_JOBS + 255) / 256, 256>>>(x, wq, wk, wv, wo);

    // 2: fused QKV projection -> fp16 planes
    gemm1t<1><<<dim3(3 * D_MODEL / BN, M / BM), 256, GEMM_SMEM>>>(
        xh, wh,
        bq, bk, bv, qh, kh, vh,
        M, D_MODEL, 0b011);

    // 3,4: tensor-core linear-attention middle
    kv_kernel<<<dim3(NBATCH * NHEAD, NSPLIT), 128>>>();
    attend_kernel<<<dim3(NROWS / 128, NBATCH * NHEAD), 256>>>();

    // 5: output projection (fp32 out)
    gemm1t<0><<<dim3(D_MODEL / BN, M / BM), 256, GEMM_SMEM>>>(
        oh, wh + (size_t)3 * D_MODEL * D_MODEL,
        bo, bo, bo, out, out, out,
        M, D_MODEL, 0);
}